// round 16
// baseline (speedup 1.0000x reference)
#include <cuda_runtime.h>
#include <cuda_fp16.h>
#include <math.h>
#include <stdint.h>

// Problem dims
#define B_SZ 4
#define L_SZ 4096
#define D_SZ 1024
#define M_SZ (B_SZ * L_SZ)   // 16384
#define N_SZ (5 * D_SZ)      // 5120
#define K_SZ D_SZ            // 1024

// Scan chunking (carry via per-block Horner over g_E; no pass2 kernel)
#define CHUNKS 32
#define TLEN   128
#define GRP    4             // scan3 group
#define GRP1   8             // scan1 group
#define NGRP   (TLEN / GRP)  // 32

// Scratch (device globals)
__device__ __half g_Z[(size_t)M_SZ * N_SZ];     // fp16 [psi_re|psi_im|phi_re|phi_im|gate]
__device__ float2 g_E[B_SZ * CHUNKS * D_SZ];
__device__ __half g_Xh[(size_t)M_SZ * K_SZ];    // fragment-major fp16 X
__device__ __half g_Wh[(size_t)N_SZ * K_SZ];    // fragment-major fp16 weights
__device__ float  g_bias[N_SZ];

// ---------------------------------------------------------------------------
// helpers
// ---------------------------------------------------------------------------
__device__ __forceinline__ uint32_t smem_u32(const void* p) {
    uint32_t a;
    asm("{ .reg .u64 t; cvta.to.shared.u64 t, %1; cvt.u32.u64 %0, t; }"
        : "=r"(a) : "l"(p));
    return a;
}
__device__ __forceinline__ unsigned pack_h2(float lo, float hi) {
    __half2 h = __floats2half2_rn(lo, hi);
    return *(unsigned*)&h;
}
__device__ __forceinline__ void mma_f16(float c[4], unsigned a0, unsigned a1,
                                        unsigned a2, unsigned a3,
                                        unsigned b0, unsigned b1) {
    asm volatile(
        "mma.sync.aligned.m16n8k16.row.col.f32.f16.f16.f32 "
        "{%0,%1,%2,%3}, {%4,%5,%6,%7}, {%8,%9}, {%0,%1,%2,%3};\n"
        : "+f"(c[0]), "+f"(c[1]), "+f"(c[2]), "+f"(c[3])
        : "r"(a0), "r"(a1), "r"(a2), "r"(a3), "r"(b0), "r"(b1));
}
__device__ __forceinline__ void cp_async16(uint32_t smem, const void* gptr) {
    asm volatile("cp.async.cg.shared.global [%0], [%1], 16;"
                 :: "r"(smem), "l"(gptr) : "memory");
}

// ---------------------------------------------------------------------------
// Merged prep kernel: cvtA (blocks [0,8192)), cvtB ([8192,13312)),
//   biascat ([13312,13332)). Fragment-major fp16 layouts for mma.m16n8k16.
// ---------------------------------------------------------------------------
#define CVTA_BLKS 8192
#define CVTB_BLKS 5120
#define BIAS_BLKS 20
#define PREP_BLKS (CVTA_BLKS + CVTB_BLKS + BIAS_BLKS)

__global__ void prep_kernel(const float* __restrict__ x,
                            const float* __restrict__ Wpsi,
                            const float* __restrict__ Wphi,
                            const float* __restrict__ Wgate,
                            const float* __restrict__ bp,
                            const float* __restrict__ bh,
                            const float* __restrict__ bg) {
    const int blk = blockIdx.x;
    if (blk < CVTA_BLKS) {
        const unsigned u = blk * 256 + threadIdx.x;       // < 2097152
        const int lane = u & 31, gid = lane >> 2, tig = lane & 3;
        const int mi = (u >> 5) & 7;
        const int kt = (u >> 8) & 63;
        const int mb = u >> 14;
        const int m = mb * 128 + mi * 16 + gid;
        const int k0 = kt * 16 + tig * 2;
        const float* xp = x + (size_t)m * K_SZ + k0;
        uint4 v;
        v.x = pack_h2(xp[0], xp[1]);
        v.y = pack_h2(xp[8 * K_SZ], xp[8 * K_SZ + 1]);
        v.z = pack_h2(xp[8], xp[9]);
        v.w = pack_h2(xp[8 * K_SZ + 8], xp[8 * K_SZ + 9]);
        ((uint4*)g_Xh)[u] = v;
    } else if (blk < CVTA_BLKS + CVTB_BLKS) {
        const unsigned u = (blk - CVTA_BLKS) * 256 + threadIdx.x;  // < 1310720
        const int lane = u & 31, gid = lane >> 2, tig = lane & 3;
        const int ni = (u >> 5) & 15;
        const int kt = (u >> 9) & 63;
        const int nb = u >> 15;
        const int n = nb * 128 + ni * 8 + gid;
        const int k0 = kt * 16 + tig * 2;
        const float* Wp;
        int n_loc;
        if (n < 2048)      { Wp = Wpsi;  n_loc = n; }
        else if (n < 4096) { Wp = Wphi;  n_loc = n - 2048; }
        else               { Wp = Wgate; n_loc = n - 4096; }
        const float* wp = Wp + (size_t)n_loc * K_SZ + k0;
        uint2 v;
        v.x = pack_h2(wp[0], wp[1]);
        v.y = pack_h2(wp[8], wp[9]);
        ((uint2*)g_Wh)[u] = v;
    } else {
        const int i = (blk - CVTA_BLKS - CVTB_BLKS) * 256 + threadIdx.x;
        float v = (i < 2048) ? bp[i] : ((i < 4096) ? bh[i - 2048] : bg[i - 4096]);
        g_bias[i] = v;
    }
}

// ---------------------------------------------------------------------------
// FP16 mma.sync GEMM: 128 threads, 4 warps (2M x 2N), warp tile 64x64.
//   CTA tile 128x128, BK=64, 3-stage cp.async, one barrier per K-iter.
//   2 CTA/SM; fp16 epilogue. (Proven R11 structure.)
// ---------------------------------------------------------------------------
#define STAGES 3
#define KTILES 16
#define STAGE_U4 2048
#define GEMM_SMEM (STAGES * 32768 + 512)

__global__ __launch_bounds__(128, 2)
void gemm_tc(const __half* __restrict__ Xp, const __half* __restrict__ Wp,
             const float* __restrict__ bias) {
    extern __shared__ __align__(16) uint4 smem4[];
    float* bsm = (float*)(smem4 + STAGES * STAGE_U4);

    const int tid = threadIdx.x;                 // 0..127
    const int lane = tid & 31, warp = tid >> 5;  // warp 0..3
    const int warpM = warp & 1, warpN = warp >> 1;
    const int gid = lane >> 2, tig = lane & 3;
    const int bn = blockIdx.x, bm = blockIdx.y;

    bsm[tid] = bias[bn * 128 + tid];

    const uint4* Ag = (const uint4*)Xp + (size_t)bm * 64 * 256;
    const uint4* Bg = (const uint4*)Wp + (size_t)bn * 64 * 256;
    const uint32_t sb = smem_u32(smem4);

    // prologue: stages 0,1 (each thread: 8 A + 8 B cp.async)
#pragma unroll
    for (int s = 0; s < STAGES - 1; s++) {
        const uint32_t base = sb + s * 32768;
#pragma unroll
        for (int i = 0; i < 8; i++) {
            const int c = i * 128 + tid;
            cp_async16(base + c * 16, Ag + (size_t)s * 1024 + c);
            cp_async16(base + 16384 + c * 16, Bg + (size_t)s * 1024 + c);
        }
        asm volatile("cp.async.commit_group;" ::: "memory");
    }

    float acc[4][8][4];
#pragma unroll
    for (int i = 0; i < 4; i++)
#pragma unroll
        for (int j = 0; j < 8; j++)
#pragma unroll
            for (int k = 0; k < 4; k++) acc[i][j][k] = 0.f;

    for (int t = 0; t < KTILES; t++) {
        asm volatile("cp.async.wait_group 1;" ::: "memory");
        __syncthreads();

        // issue loads for tile t+2 into just-freed stage
        if (t + STAGES - 1 < KTILES) {
            const int tt = t + STAGES - 1;
            const uint32_t base = sb + (tt % STAGES) * 32768;
#pragma unroll
            for (int i = 0; i < 8; i++) {
                const int c = i * 128 + tid;
                cp_async16(base + c * 16, Ag + (size_t)tt * 1024 + c);
                cp_async16(base + 16384 + c * 16, Bg + (size_t)tt * 1024 + c);
            }
        }
        asm volatile("cp.async.commit_group;" ::: "memory");

        const uint4* As = smem4 + (t % STAGES) * STAGE_U4;
        const uint2* Bs = (const uint2*)(As + 1024);

#pragma unroll
        for (int ktl = 0; ktl < 4; ktl++) {
            uint2 bq[8];
#pragma unroll
            for (int ni = 0; ni < 8; ni++)
                bq[ni] = Bs[(ktl * 16 + warpN * 8 + ni) * 32 + lane];
            uint4 aq[4];
#pragma unroll
            for (int mi = 0; mi < 4; mi++)
                aq[mi] = As[(ktl * 8 + warpM * 4 + mi) * 32 + lane];
#pragma unroll
            for (int mi = 0; mi < 4; mi++)
#pragma unroll
                for (int ni = 0; ni < 8; ni++)
                    mma_f16(acc[mi][ni], aq[mi].x, aq[mi].y, aq[mi].z, aq[mi].w,
                            bq[ni].x, bq[ni].y);
        }
    }

    // Epilogue: bias + fp16 store (warp tile 64x64)
    const int m0 = bm * 128, n0 = bn * 128;
#pragma unroll
    for (int mi = 0; mi < 4; mi++) {
#pragma unroll
        for (int ni = 0; ni < 8; ni++) {
            const int row = m0 + warpM * 64 + mi * 16 + gid;
            const int colL = warpN * 64 + ni * 8 + tig * 2;
            const float bv0 = bsm[colL];
            const float bv1 = bsm[colL + 1];
            const unsigned v0 = pack_h2(acc[mi][ni][0] + bv0, acc[mi][ni][1] + bv1);
            const unsigned v1 = pack_h2(acc[mi][ni][2] + bv0, acc[mi][ni][3] + bv1);
            *(unsigned*)&g_Z[(size_t)row * N_SZ + n0 + colL]       = v0;
            *(unsigned*)&g_Z[(size_t)(row + 8) * N_SZ + n0 + colL] = v1;
        }
    }
}

// ---------------------------------------------------------------------------
// Scan pass1: per-chunk local ends (TLEN=128); grid (CHUNKS, B_SZ, 4), 256 thr
// ---------------------------------------------------------------------------
__global__ __launch_bounds__(256)
void scan_pass1(const float* __restrict__ omega, const float* __restrict__ lg,
                const float* __restrict__ dtp) {
    const int d = blockIdx.z * 256 + threadIdx.x;
    const int c = blockIdx.x;
    const int b = blockIdx.y;
    const float dt = fabsf(*dtp);
    const float decay = expf(-expf(lg[d]) * dt);
    const float ang = omega[d] * dt;
    const float rre = decay * cosf(ang), rim = decay * sinf(ang);

    const __half* Zrow = g_Z + (size_t)(b * L_SZ + c * TLEN) * N_SZ + d;
    float hre = 0.f, him = 0.f;
    for (int g = 0; g < TLEN / GRP1; g++) {
        float Lp[GRP1], Li[GRP1], Lg[GRP1];
#pragma unroll
        for (int i = 0; i < GRP1; i++) {
            const __half* z = Zrow + (size_t)i * N_SZ;
            Lp[i] = __half2float(z[0]);
            Li[i] = __half2float(z[1024]);
            Lg[i] = __half2float(z[4096]);
        }
#pragma unroll
        for (int i = 0; i < GRP1; i++) {
            const float s = 1.f / (1.f + expf(-Lg[i]));
            const float ure = s * Lp[i], uim = s * Li[i];
            const float nre = rre * hre - rim * him + ure;
            him = rre * him + rim * hre + uim;
            hre = nre;
        }
        Zrow += (size_t)GRP1 * N_SZ;
    }
    g_E[(b * CHUNKS + c) * D_SZ + d] = make_float2(hre, him);
}

// ---------------------------------------------------------------------------
// Fused: Horner carry from g_E + scan + standardization + phi contraction.
//   - carry: batched 8-wide independent loads + FMA chain
//   - pipelined: next group's gated psi (Ur/Ui) loads issued before the
//     reduction barriers; phi loads issued at group start, used after.
//   - red/bc double-buffered by group parity (no trailing barrier).
// ---------------------------------------------------------------------------
__global__ __launch_bounds__(1024)
void scan3_proj(const float* __restrict__ omega, const float* __restrict__ lg,
                const float* __restrict__ dtp, float* __restrict__ out) {
    const int d = threadIdx.x;
    const int lane = d & 31, warp = d >> 5;
    const int c = blockIdx.x;
    const int b = blockIdx.y;

    __shared__ float red[2][16][32];
    __shared__ float bc[2][16];

    const float dt = fabsf(*dtp);
    const float ex = expf(lg[d]);
    const float decay = expf(-ex * dt);
    const float ang = omega[d] * dt;
    const float rre = decay * cosf(ang), rim = decay * sinf(ang);

    // rT = r^TLEN
    const float decayT = expf(-ex * dt * (float)TLEN);
    const float angT = omega[d] * dt * (float)TLEN;
    const float rTre = decayT * cosf(angT), rTim = decayT * sinf(angT);

    // Horner carry over previous chunk ends, batched 8-wide
    float hre = 0.f, him = 0.f;
    {
        const float2* Eb = g_E + (size_t)b * CHUNKS * D_SZ + d;
        int j = 0;
        while (j < c) {
            float2 eb[8];
            const int nb = (c - j < 8) ? (c - j) : 8;
#pragma unroll
            for (int i = 0; i < 8; i++)
                if (i < nb) eb[i] = Eb[(size_t)(j + i) * D_SZ];
#pragma unroll
            for (int i = 0; i < 8; i++) {
                if (i < nb) {
                    const float nre = eb[i].x + rTre * hre - rTim * him;
                    him = eb[i].y + rTre * him + rTim * hre;
                    hre = nre;
                }
            }
            j += nb;
        }
    }

    const __half* Zrow = g_Z + (size_t)(b * L_SZ + c * TLEN) * N_SZ + d;
    float* orow = out + (size_t)(b * L_SZ + c * TLEN) * D_SZ + d;

    const float invD = 1.f / (float)D_SZ;

    // gated psi double buffers (sigmoid applied at load to save registers)
    float Ur[2][GRP], Ui[2][GRP];
#pragma unroll
    for (int i = 0; i < GRP; i++) {
        const __half* z = Zrow + (size_t)i * N_SZ;
        const float gt = __half2float(z[4096]);
        const float s = 1.f / (1.f + expf(-gt));
        Ur[0][i] = s * __half2float(z[0]);
        Ui[0][i] = s * __half2float(z[1024]);
    }

#pragma unroll 2
    for (int g = 0; g < NGRP; g++) {
        const int p = g & 1;

        // phi loads for this group (used only after reduction)
        float Pr[GRP], Pi[GRP];
#pragma unroll
        for (int i = 0; i < GRP; i++) {
            const __half* z = Zrow + (size_t)i * N_SZ;
            Pr[i] = __half2float(z[2048]);
            Pi[i] = __half2float(z[3072]);
        }

        // recurrence for this group
        float hr[GRP], hi[GRP];
#pragma unroll
        for (int i = 0; i < GRP; i++) {
            const float nre = rre * hre - rim * him + Ur[p][i];
            him = rre * him + rim * hre + Ui[p][i];
            hre = nre;
            hr[i] = hre; hi[i] = him;
        }

        // prefetch next group's gated psi (covers DRAM latency w/ reduction)
        if (g + 1 < NGRP) {
            const __half* Znext = Zrow + (size_t)GRP * N_SZ;
#pragma unroll
            for (int i = 0; i < GRP; i++) {
                const __half* z = Znext + (size_t)i * N_SZ;
                const float gt = __half2float(z[4096]);
                const float s = 1.f / (1.f + expf(-gt));
                Ur[p ^ 1][i] = s * __half2float(z[0]);
                Ui[p ^ 1][i] = s * __half2float(z[1024]);
            }
        }

        // block reduction: 16 chains (4 steps x {sr, si, sr2, si2})
        float v[16];
#pragma unroll
        for (int i = 0; i < GRP; i++) {
            v[i * 4 + 0] = hr[i];
            v[i * 4 + 1] = hi[i];
            v[i * 4 + 2] = hr[i] * hr[i];
            v[i * 4 + 3] = hi[i] * hi[i];
        }
#pragma unroll
        for (int off = 16; off > 0; off >>= 1)
#pragma unroll
            for (int j = 0; j < 16; j++)
                v[j] += __shfl_xor_sync(0xFFFFFFFFu, v[j], off);
        if (lane == 0)
#pragma unroll
            for (int j = 0; j < 16; j++) red[p][j][warp] = v[j];
        __syncthreads();

        if (warp < 4) {
#pragma unroll
            for (int jj = 0; jj < 4; jj++) {
                const int j = warp * 4 + jj;
                float t = red[p][j][lane];
#pragma unroll
                for (int off = 16; off > 0; off >>= 1)
                    t += __shfl_xor_sync(0xFFFFFFFFu, t, off);
                if (lane == 0) bc[p][j] = t;
            }
        }
        __syncthreads();

#pragma unroll
        for (int i = 0; i < GRP; i++) {
            const float mre = bc[p][i * 4 + 0] * invD;
            const float mim = bc[p][i * 4 + 1] * invD;
            const float vre = fmaxf(bc[p][i * 4 + 2] * invD - mre * mre, 0.f);
            const float vim = fmaxf(bc[p][i * 4 + 3] * invD - mim * mim, 0.f);
            const float ivr = 1.f / (sqrtf(vre) + 1e-6f);
            const float ivi = 1.f / (sqrtf(vim) + 1e-6f);
            const float zre = (hr[i] - mre) * ivr;
            const float zim = (hi[i] - mim) * ivi;
            orow[(size_t)i * D_SZ] = zre * Pr[i] + zim * Pi[i];
        }
        // no trailing barrier: red/bc are double-buffered by parity

        Zrow += (size_t)GRP * N_SZ;
        orow += (size_t)GRP * D_SZ;
    }
}

// ---------------------------------------------------------------------------
extern "C" void kernel_launch(void* const* d_in, const int* in_sizes, int n_in,
                              void* d_out, int out_size) {
    const float* x     = (const float*)d_in[0];
    const float* omega = (const float*)d_in[1];
    const float* lg    = (const float*)d_in[2];
    const float* dt    = (const float*)d_in[3];
    const float* Wpsi  = (const float*)d_in[4];
    const float* bpsi  = (const float*)d_in[5];
    const float* Wphi  = (const float*)d_in[6];
    const float* bphi  = (const float*)d_in[7];
    const float* Wgate = (const float*)d_in[8];
    const float* bgate = (const float*)d_in[9];
    float* out = (float*)d_out;

    cudaFuncSetAttribute(gemm_tc, cudaFuncAttributeMaxDynamicSharedMemorySize,
                         GEMM_SMEM);

    __half* Xh;  cudaGetSymbolAddress((void**)&Xh, g_Xh);
    __half* Wh;  cudaGetSymbolAddress((void**)&Wh, g_Wh);
    float* bb;   cudaGetSymbolAddress((void**)&bb, g_bias);

    prep_kernel<<<PREP_BLKS, 256>>>(x, Wpsi, Wphi, Wgate, bpsi, bphi, bgate);

    gemm_tc<<<dim3(40, 128), 128, GEMM_SMEM>>>(Xh, Wh, bb);

    scan_pass1<<<dim3(CHUNKS, B_SZ, 4), 256>>>(omega, lg, dt);
    scan3_proj<<<dim3(CHUNKS, B_SZ), 1024>>>(omega, lg, dt, out);
}

// round 17
// speedup vs baseline: 1.0792x; 1.0792x over previous
#include <cuda_runtime.h>
#include <cuda_fp16.h>
#include <math.h>
#include <stdint.h>

// Problem dims
#define B_SZ 4
#define L_SZ 4096
#define D_SZ 1024
#define M_SZ (B_SZ * L_SZ)   // 16384
#define N_SZ (5 * D_SZ)      // 5120
#define K_SZ D_SZ            // 1024

// Scan chunking (carry via per-block Horner over g_E; no pass2 kernel)
#define CHUNKS 32
#define TLEN   128
#define GRP    4             // scan3 group
#define GRP1   8             // scan1 group
#define NGRP   (TLEN / GRP)  // 32

// Scratch (device globals)
__device__ __half g_Z[(size_t)M_SZ * N_SZ];     // fp16 [psi_re|psi_im|phi_re|phi_im|gate]
__device__ float2 g_E[B_SZ * CHUNKS * D_SZ];
__device__ __half g_Xh[(size_t)M_SZ * K_SZ];    // fragment-major fp16 X
__device__ __half g_Wh[(size_t)N_SZ * K_SZ];    // fragment-major fp16 weights
__device__ float  g_bias[N_SZ];

// ---------------------------------------------------------------------------
// helpers
// ---------------------------------------------------------------------------
__device__ __forceinline__ uint32_t smem_u32(const void* p) {
    uint32_t a;
    asm("{ .reg .u64 t; cvta.to.shared.u64 t, %1; cvt.u32.u64 %0, t; }"
        : "=r"(a) : "l"(p));
    return a;
}
__device__ __forceinline__ unsigned pack_h2(float lo, float hi) {
    __half2 h = __floats2half2_rn(lo, hi);
    return *(unsigned*)&h;
}
__device__ __forceinline__ void mma_f16(float c[4], unsigned a0, unsigned a1,
                                        unsigned a2, unsigned a3,
                                        unsigned b0, unsigned b1) {
    asm volatile(
        "mma.sync.aligned.m16n8k16.row.col.f32.f16.f16.f32 "
        "{%0,%1,%2,%3}, {%4,%5,%6,%7}, {%8,%9}, {%0,%1,%2,%3};\n"
        : "+f"(c[0]), "+f"(c[1]), "+f"(c[2]), "+f"(c[3])
        : "r"(a0), "r"(a1), "r"(a2), "r"(a3), "r"(b0), "r"(b1));
}
__device__ __forceinline__ void cp_async16(uint32_t smem, const void* gptr) {
    asm volatile("cp.async.cg.shared.global [%0], [%1], 16;"
                 :: "r"(smem), "l"(gptr) : "memory");
}

// ---------------------------------------------------------------------------
// Merged prep kernel: cvtA (blocks [0,8192)), cvtB ([8192,13312)),
//   biascat ([13312,13332)). Fragment-major fp16 layouts for mma.m16n8k16.
// ---------------------------------------------------------------------------
#define CVTA_BLKS 8192
#define CVTB_BLKS 5120
#define BIAS_BLKS 20
#define PREP_BLKS (CVTA_BLKS + CVTB_BLKS + BIAS_BLKS)

__global__ void prep_kernel(const float* __restrict__ x,
                            const float* __restrict__ Wpsi,
                            const float* __restrict__ Wphi,
                            const float* __restrict__ Wgate,
                            const float* __restrict__ bp,
                            const float* __restrict__ bh,
                            const float* __restrict__ bg) {
    const int blk = blockIdx.x;
    if (blk < CVTA_BLKS) {
        const unsigned u = blk * 256 + threadIdx.x;       // < 2097152
        const int lane = u & 31, gid = lane >> 2, tig = lane & 3;
        const int mi = (u >> 5) & 7;
        const int kt = (u >> 8) & 63;
        const int mb = u >> 14;
        const int m = mb * 128 + mi * 16 + gid;
        const int k0 = kt * 16 + tig * 2;
        const float* xp = x + (size_t)m * K_SZ + k0;
        uint4 v;
        v.x = pack_h2(xp[0], xp[1]);
        v.y = pack_h2(xp[8 * K_SZ], xp[8 * K_SZ + 1]);
        v.z = pack_h2(xp[8], xp[9]);
        v.w = pack_h2(xp[8 * K_SZ + 8], xp[8 * K_SZ + 9]);
        ((uint4*)g_Xh)[u] = v;
    } else if (blk < CVTA_BLKS + CVTB_BLKS) {
        const unsigned u = (blk - CVTA_BLKS) * 256 + threadIdx.x;  // < 1310720
        const int lane = u & 31, gid = lane >> 2, tig = lane & 3;
        const int ni = (u >> 5) & 15;
        const int kt = (u >> 9) & 63;
        const int nb = u >> 15;
        const int n = nb * 128 + ni * 8 + gid;
        const int k0 = kt * 16 + tig * 2;
        const float* Wp;
        int n_loc;
        if (n < 2048)      { Wp = Wpsi;  n_loc = n; }
        else if (n < 4096) { Wp = Wphi;  n_loc = n - 2048; }
        else               { Wp = Wgate; n_loc = n - 4096; }
        const float* wp = Wp + (size_t)n_loc * K_SZ + k0;
        uint2 v;
        v.x = pack_h2(wp[0], wp[1]);
        v.y = pack_h2(wp[8], wp[9]);
        ((uint2*)g_Wh)[u] = v;
    } else {
        const int i = (blk - CVTA_BLKS - CVTB_BLKS) * 256 + threadIdx.x;
        float v = (i < 2048) ? bp[i] : ((i < 4096) ? bh[i - 2048] : bg[i - 4096]);
        g_bias[i] = v;
    }
}

// ---------------------------------------------------------------------------
// FP16 mma.sync GEMM: 128 threads, 4 warps (2M x 2N), warp tile 64x64.
//   CTA tile 128x128, BK=64, 3-stage cp.async, one barrier per K-iter.
//   2 CTA/SM; fp16 epilogue. (Proven R11 structure.)
// ---------------------------------------------------------------------------
#define STAGES 3
#define KTILES 16
#define STAGE_U4 2048
#define GEMM_SMEM (STAGES * 32768 + 512)

__global__ __launch_bounds__(128, 2)
void gemm_tc(const __half* __restrict__ Xp, const __half* __restrict__ Wp,
             const float* __restrict__ bias) {
    extern __shared__ __align__(16) uint4 smem4[];
    float* bsm = (float*)(smem4 + STAGES * STAGE_U4);

    const int tid = threadIdx.x;                 // 0..127
    const int lane = tid & 31, warp = tid >> 5;  // warp 0..3
    const int warpM = warp & 1, warpN = warp >> 1;
    const int gid = lane >> 2, tig = lane & 3;
    const int bn = blockIdx.x, bm = blockIdx.y;

    bsm[tid] = bias[bn * 128 + tid];

    const uint4* Ag = (const uint4*)Xp + (size_t)bm * 64 * 256;
    const uint4* Bg = (const uint4*)Wp + (size_t)bn * 64 * 256;
    const uint32_t sb = smem_u32(smem4);

    // prologue: stages 0,1 (each thread: 8 A + 8 B cp.async)
#pragma unroll
    for (int s = 0; s < STAGES - 1; s++) {
        const uint32_t base = sb + s * 32768;
#pragma unroll
        for (int i = 0; i < 8; i++) {
            const int c = i * 128 + tid;
            cp_async16(base + c * 16, Ag + (size_t)s * 1024 + c);
            cp_async16(base + 16384 + c * 16, Bg + (size_t)s * 1024 + c);
        }
        asm volatile("cp.async.commit_group;" ::: "memory");
    }

    float acc[4][8][4];
#pragma unroll
    for (int i = 0; i < 4; i++)
#pragma unroll
        for (int j = 0; j < 8; j++)
#pragma unroll
            for (int k = 0; k < 4; k++) acc[i][j][k] = 0.f;

    for (int t = 0; t < KTILES; t++) {
        asm volatile("cp.async.wait_group 1;" ::: "memory");
        __syncthreads();

        // issue loads for tile t+2 into just-freed stage
        if (t + STAGES - 1 < KTILES) {
            const int tt = t + STAGES - 1;
            const uint32_t base = sb + (tt % STAGES) * 32768;
#pragma unroll
            for (int i = 0; i < 8; i++) {
                const int c = i * 128 + tid;
                cp_async16(base + c * 16, Ag + (size_t)tt * 1024 + c);
                cp_async16(base + 16384 + c * 16, Bg + (size_t)tt * 1024 + c);
            }
        }
        asm volatile("cp.async.commit_group;" ::: "memory");

        const uint4* As = smem4 + (t % STAGES) * STAGE_U4;
        const uint2* Bs = (const uint2*)(As + 1024);

#pragma unroll
        for (int ktl = 0; ktl < 4; ktl++) {
            uint2 bq[8];
#pragma unroll
            for (int ni = 0; ni < 8; ni++)
                bq[ni] = Bs[(ktl * 16 + warpN * 8 + ni) * 32 + lane];
            uint4 aq[4];
#pragma unroll
            for (int mi = 0; mi < 4; mi++)
                aq[mi] = As[(ktl * 8 + warpM * 4 + mi) * 32 + lane];
#pragma unroll
            for (int mi = 0; mi < 4; mi++)
#pragma unroll
                for (int ni = 0; ni < 8; ni++)
                    mma_f16(acc[mi][ni], aq[mi].x, aq[mi].y, aq[mi].z, aq[mi].w,
                            bq[ni].x, bq[ni].y);
        }
    }

    // Epilogue: bias + fp16 store (warp tile 64x64)
    const int m0 = bm * 128, n0 = bn * 128;
#pragma unroll
    for (int mi = 0; mi < 4; mi++) {
#pragma unroll
        for (int ni = 0; ni < 8; ni++) {
            const int row = m0 + warpM * 64 + mi * 16 + gid;
            const int colL = warpN * 64 + ni * 8 + tig * 2;
            const float bv0 = bsm[colL];
            const float bv1 = bsm[colL + 1];
            const unsigned v0 = pack_h2(acc[mi][ni][0] + bv0, acc[mi][ni][1] + bv1);
            const unsigned v1 = pack_h2(acc[mi][ni][2] + bv0, acc[mi][ni][3] + bv1);
            *(unsigned*)&g_Z[(size_t)row * N_SZ + n0 + colL]       = v0;
            *(unsigned*)&g_Z[(size_t)(row + 8) * N_SZ + n0 + colL] = v1;
        }
    }
}

// ---------------------------------------------------------------------------
// Scan pass1: per-chunk local ends (TLEN=128); grid (CHUNKS, B_SZ, 4), 256 thr
// ---------------------------------------------------------------------------
__global__ __launch_bounds__(256)
void scan_pass1(const float* __restrict__ omega, const float* __restrict__ lg,
                const float* __restrict__ dtp) {
    const int d = blockIdx.z * 256 + threadIdx.x;
    const int c = blockIdx.x;
    const int b = blockIdx.y;
    const float dt = fabsf(*dtp);
    const float decay = expf(-expf(lg[d]) * dt);
    const float ang = omega[d] * dt;
    const float rre = decay * cosf(ang), rim = decay * sinf(ang);

    const __half* Zrow = g_Z + (size_t)(b * L_SZ + c * TLEN) * N_SZ + d;
    float hre = 0.f, him = 0.f;
    for (int g = 0; g < TLEN / GRP1; g++) {
        float Lp[GRP1], Li[GRP1], Lg[GRP1];
#pragma unroll
        for (int i = 0; i < GRP1; i++) {
            const __half* z = Zrow + (size_t)i * N_SZ;
            Lp[i] = __half2float(z[0]);
            Li[i] = __half2float(z[1024]);
            Lg[i] = __half2float(z[4096]);
        }
#pragma unroll
        for (int i = 0; i < GRP1; i++) {
            const float s = 1.f / (1.f + expf(-Lg[i]));
            const float ure = s * Lp[i], uim = s * Li[i];
            const float nre = rre * hre - rim * him + ure;
            him = rre * him + rim * hre + uim;
            hre = nre;
        }
        Zrow += (size_t)GRP1 * N_SZ;
    }
    g_E[(b * CHUNKS + c) * D_SZ + d] = make_float2(hre, him);
}

// ---------------------------------------------------------------------------
// Fused: Horner carry from g_E + scan + standardization + phi contraction.
//   Simple single-buffer structure (R14-proven); carry batched 8-wide.
// ---------------------------------------------------------------------------
__global__ __launch_bounds__(1024)
void scan3_proj(const float* __restrict__ omega, const float* __restrict__ lg,
                const float* __restrict__ dtp, float* __restrict__ out) {
    const int d = threadIdx.x;
    const int lane = d & 31, warp = d >> 5;
    const int c = blockIdx.x;
    const int b = blockIdx.y;

    __shared__ float red[16][32];
    __shared__ float bc[16];

    const float dt = fabsf(*dtp);
    const float ex = expf(lg[d]);
    const float decay = expf(-ex * dt);
    const float ang = omega[d] * dt;
    const float rre = decay * cosf(ang), rim = decay * sinf(ang);

    // rT = r^TLEN
    const float decayT = expf(-ex * dt * (float)TLEN);
    const float angT = omega[d] * dt * (float)TLEN;
    const float rTre = decayT * cosf(angT), rTim = decayT * sinf(angT);

    // Horner carry over previous chunk ends, batched 8-wide
    float hre = 0.f, him = 0.f;
    {
        const float2* Eb = g_E + (size_t)b * CHUNKS * D_SZ + d;
        int j = 0;
        while (j < c) {
            float2 eb[8];
            const int nb = (c - j < 8) ? (c - j) : 8;
#pragma unroll
            for (int i = 0; i < 8; i++)
                if (i < nb) eb[i] = Eb[(size_t)(j + i) * D_SZ];
#pragma unroll
            for (int i = 0; i < 8; i++) {
                if (i < nb) {
                    const float nre = eb[i].x + rTre * hre - rTim * him;
                    him = eb[i].y + rTre * him + rTim * hre;
                    hre = nre;
                }
            }
            j += nb;
        }
    }

    const __half* Zrow = g_Z + (size_t)(b * L_SZ + c * TLEN) * N_SZ + d;
    float* orow = out + (size_t)(b * L_SZ + c * TLEN) * D_SZ + d;

    const float invD = 1.f / (float)D_SZ;

    for (int g = 0; g < NGRP; g++) {
        float Lp[GRP], Li[GRP], Lg[GRP], Pr[GRP], Pi[GRP];
#pragma unroll
        for (int i = 0; i < GRP; i++) {
            const __half* z = Zrow + (size_t)i * N_SZ;
            Lp[i] = __half2float(z[0]);
            Li[i] = __half2float(z[1024]);
            Lg[i] = __half2float(z[4096]);
            Pr[i] = __half2float(z[2048]);
            Pi[i] = __half2float(z[3072]);
        }

        float hr[GRP], hi[GRP];
#pragma unroll
        for (int i = 0; i < GRP; i++) {
            const float s = 1.f / (1.f + expf(-Lg[i]));
            const float ure = s * Lp[i], uim = s * Li[i];
            const float nre = rre * hre - rim * him + ure;
            him = rre * him + rim * hre + uim;
            hre = nre;
            hr[i] = hre; hi[i] = him;
        }

        float v[16];
#pragma unroll
        for (int i = 0; i < GRP; i++) {
            v[i * 4 + 0] = hr[i];
            v[i * 4 + 1] = hi[i];
            v[i * 4 + 2] = hr[i] * hr[i];
            v[i * 4 + 3] = hi[i] * hi[i];
        }
#pragma unroll
        for (int off = 16; off > 0; off >>= 1)
#pragma unroll
            for (int j = 0; j < 16; j++)
                v[j] += __shfl_xor_sync(0xFFFFFFFFu, v[j], off);
        if (lane == 0)
#pragma unroll
            for (int j = 0; j < 16; j++) red[j][warp] = v[j];
        __syncthreads();

        if (warp < 4) {
#pragma unroll
            for (int jj = 0; jj < 4; jj++) {
                const int j = warp * 4 + jj;
                float t = red[j][lane];
#pragma unroll
                for (int off = 16; off > 0; off >>= 1)
                    t += __shfl_xor_sync(0xFFFFFFFFu, t, off);
                if (lane == 0) bc[j] = t;
            }
        }
        __syncthreads();

#pragma unroll
        for (int i = 0; i < GRP; i++) {
            const float mre = bc[i * 4 + 0] * invD;
            const float mim = bc[i * 4 + 1] * invD;
            const float vre = fmaxf(bc[i * 4 + 2] * invD - mre * mre, 0.f);
            const float vim = fmaxf(bc[i * 4 + 3] * invD - mim * mim, 0.f);
            const float ivr = 1.f / (sqrtf(vre) + 1e-6f);
            const float ivi = 1.f / (sqrtf(vim) + 1e-6f);
            const float zre = (hr[i] - mre) * ivr;
            const float zim = (hi[i] - mim) * ivi;
            orow[(size_t)i * D_SZ] = zre * Pr[i] + zim * Pi[i];
        }
        __syncthreads();

        Zrow += (size_t)GRP * N_SZ;
        orow += (size_t)GRP * D_SZ;
    }
}

// ---------------------------------------------------------------------------
extern "C" void kernel_launch(void* const* d_in, const int* in_sizes, int n_in,
                              void* d_out, int out_size) {
    const float* x     = (const float*)d_in[0];
    const float* omega = (const float*)d_in[1];
    const float* lg    = (const float*)d_in[2];
    const float* dt    = (const float*)d_in[3];
    const float* Wpsi  = (const float*)d_in[4];
    const float* bpsi  = (const float*)d_in[5];
    const float* Wphi  = (const float*)d_in[6];
    const float* bphi  = (const float*)d_in[7];
    const float* Wgate = (const float*)d_in[8];
    const float* bgate = (const float*)d_in[9];
    float* out = (float*)d_out;

    cudaFuncSetAttribute(gemm_tc, cudaFuncAttributeMaxDynamicSharedMemorySize,
                         GEMM_SMEM);

    __half* Xh;  cudaGetSymbolAddress((void**)&Xh, g_Xh);
    __half* Wh;  cudaGetSymbolAddress((void**)&Wh, g_Wh);
    float* bb;   cudaGetSymbolAddress((void**)&bb, g_bias);

    prep_kernel<<<PREP_BLKS, 256>>>(x, Wpsi, Wphi, Wgate, bpsi, bphi, bgate);

    gemm_tc<<<dim3(40, 128), 128, GEMM_SMEM>>>(Xh, Wh, bb);

    scan_pass1<<<dim3(CHUNKS, B_SZ, 4), 256>>>(omega, lg, dt);
    scan3_proj<<<dim3(CHUNKS, B_SZ), 1024>>>(omega, lg, dt, out);
}